// round 5
// baseline (speedup 1.0000x reference)
#include <cuda_runtime.h>
#include <cuda_bf16.h>

// GHM-C loss, single pass:
//   t in {0,1} exactly -> z = (1-2t)*x, g = sigmoid(z), bce = softplus(z).
//   result = sum_b S_b / max(cnt_b * nonempty, 1e-4)  where S_b = sum of bce in bin b.
// Pass 1: per-thread private shared histograms (conflict-free, no atomics in hot loop),
//         block tree-reduce, double global atomics (10 per block).
// Pass 2: tiny finalize kernel -> scalar.

#define BINS      10
#define NTHREADS  256
#define NBLOCKS   888          // 148 SMs * 6 blocks

__device__ double g_cnt[BINS];
__device__ double g_sum[BINS];

__global__ void ghm_zero_kernel() {
    int t = threadIdx.x;
    if (t < BINS) { g_cnt[t] = 0.0; g_sum[t] = 0.0; }
}

__global__ __launch_bounds__(NTHREADS, 6)
void ghm_main_kernel(const float4* __restrict__ xv4,
                     const float4* __restrict__ tv4,
                     int nvec, int n)
{
    __shared__ float2 hist[BINS * NTHREADS];   // [bin][tid] : {count, bce_sum}

    const int tid = threadIdx.x;
    #pragma unroll
    for (int b = 0; b < BINS; ++b)
        hist[b * NTHREADS + tid] = make_float2(0.0f, 0.0f);
    __syncthreads();

    const int stride = gridDim.x * NTHREADS;
    for (int i = blockIdx.x * NTHREADS + tid; i < nvec; i += stride) {
        float4 xv = xv4[i];
        float4 tv = tv4[i];
        float xs[4] = {xv.x, xv.y, xv.z, xv.w};
        float ts[4] = {tv.x, tv.y, tv.z, tv.w};
        #pragma unroll
        for (int k = 0; k < 4; ++k) {
            float xk = xs[k];
            float z  = (ts[k] > 0.5f) ? -xk : xk;   // z = (1-2t)*x, t exactly 0/1
            float az = fabsf(z);
            float u  = __expf(-az);                 // e^{-|z|}  (MUFU.EX2)
            float w  = 1.0f + u;
            float r  = __fdividef(1.0f, w);         // MUFU.RCP path
            float ur = u * r;                       // sigmoid(-|z|)
            float g  = (z >= 0.0f) ? (1.0f - ur) : ur;   // sigmoid(z)
            int bin  = (int)(g * 9.9999f);          // floor, g >= 0
            bin = min(bin, BINS - 1);               // guard approx-rcp overshoot
            float bce = fmaxf(z, 0.0f) + __logf(w); // softplus(z) (MUFU.LG2)

            float2* slot = &hist[bin * NTHREADS + tid];
            float2 h = *slot;
            h.x += 1.0f;
            h.y += bce;
            *slot = h;
        }
    }

    // scalar tail (n not multiple of 4) -- block 0 only
    if (blockIdx.x == 0) {
        int base = nvec * 4;
        int rem  = n - base;
        if (tid < rem) {
            const float* xf = (const float*)xv4;
            const float* tf = (const float*)tv4;
            float xk = xf[base + tid];
            float z  = (tf[base + tid] > 0.5f) ? -xk : xk;
            float az = fabsf(z);
            float u  = __expf(-az);
            float w  = 1.0f + u;
            float r  = __fdividef(1.0f, w);
            float ur = u * r;
            float g  = (z >= 0.0f) ? (1.0f - ur) : ur;
            int bin  = min((int)(g * 9.9999f), BINS - 1);
            float bce = fmaxf(z, 0.0f) + __logf(w);
            float2* slot = &hist[bin * NTHREADS + tid];
            float2 h = *slot;
            h.x += 1.0f;
            h.y += bce;
            *slot = h;
        }
    }
    __syncthreads();

    // tree-reduce over the 256 private histograms
    for (int s = NTHREADS / 2; s > 0; s >>= 1) {
        if (tid < s) {
            #pragma unroll
            for (int b = 0; b < BINS; ++b) {
                float2 a = hist[b * NTHREADS + tid];
                float2 c = hist[b * NTHREADS + tid + s];
                a.x += c.x;
                a.y += c.y;
                hist[b * NTHREADS + tid] = a;
            }
        }
        __syncthreads();
    }

    if (tid < BINS) {
        atomicAdd(&g_cnt[tid], (double)hist[tid * NTHREADS].x);
        atomicAdd(&g_sum[tid], (double)hist[tid * NTHREADS].y);
    }
}

__global__ void ghm_finalize_kernel(float* __restrict__ out) {
    if (threadIdx.x == 0) {
        double ne = 0.0;
        #pragma unroll
        for (int b = 0; b < BINS; ++b)
            if (g_cnt[b] > 0.0) ne += 1.0;
        double res = 0.0;
        #pragma unroll
        for (int b = 0; b < BINS; ++b) {
            double gd = g_cnt[b] * ne;
            if (gd < 1e-4) gd = 1e-4;
            res += g_sum[b] / gd;
        }
        out[0] = (float)res;
    }
}

extern "C" void kernel_launch(void* const* d_in, const int* in_sizes, int n_in,
                              void* d_out, int out_size) {
    const float* x = (const float*)d_in[0];
    const float* t = (const float*)d_in[1];
    int n    = in_sizes[0];
    int nvec = n >> 2;

    ghm_zero_kernel<<<1, 32>>>();
    ghm_main_kernel<<<NBLOCKS, NTHREADS>>>((const float4*)x, (const float4*)t, nvec, n);
    ghm_finalize_kernel<<<1, 32>>>((float*)d_out);
}

// round 6
// speedup vs baseline: 1.0086x; 1.0086x over previous
#include <cuda_runtime.h>
#include <cuda_bf16.h>

// GHM-C loss, fully fused single kernel:
//   t in {0,1} exactly -> z = (1-2t)*x, g = sigmoid(z), bce = softplus(z)
//   result = sum_b (ln2 * P_b) / max(cnt_b * nonempty, 1e-4)
//   where P_b = sum over bin b of  max(z2,0) + log2(1 + 2^{-|z2|}),  z2 = z*log2e.
//
// Pass structure inside ONE kernel:
//   - per-thread private shared histogram slots (conflict-free: bank = tid%32,
//     independent of bin) -> no atomics in the hot loop
//   - block tree-reduce -> 10 double global atomicAdds per block
//   - threadfence + done-counter: the LAST block finalizes the scalar and
//     resets the global accumulators for the next (graph-replayed) call.

#define BINS      10
#define NTHREADS  256
#define NBLOCKS   888          // 148 SMs * 6 resident blocks -> 1 wave
#define LOG2E_F   1.4426950408889634f
#define LN2_D     0.6931471805599453

__device__ double        g_cnt[BINS];   // zero-initialized at module load
__device__ double        g_sum[BINS];
__device__ unsigned int  g_done;

__device__ __forceinline__ void ghm_elem(float xk, float tk,
                                         float2* __restrict__ hist_tid)
{
    // z2 = (1-2t)*x*log2e   (t is exactly 0 or 1)
    float z2 = (tk > 0.5f) ? -xk : xk;
    z2 *= LOG2E_F;
    float u  = exp2f(-fabsf(z2));            // MUFU.EX2, u in (0,1]
    float w  = 1.0f + u;
    float ur = u * __fdividef(1.0f, w);      // sigmoid(-|z2|), MUFU.RCP path
    float q  = ur * 9.9999f;
    float bi = (z2 >= 0.0f) ? (9.9999f - q) : q;   // g*9.9999
    int bin  = min((int)bi, BINS - 1);
    float p  = fmaxf(z2, 0.0f) + __log2f(w); // softplus(z)/ln2  (MUFU.LG2)

    float2* slot = &hist_tid[bin * NTHREADS];
    float2 h = *slot;
    h.x += 1.0f;
    h.y += p;
    *slot = h;
}

__global__ __launch_bounds__(NTHREADS, 6)
void ghm_fused_kernel(const float4* __restrict__ xv4,
                      const float4* __restrict__ tv4,
                      int nvec, int n,
                      float* __restrict__ out)
{
    __shared__ float2 hist[BINS * NTHREADS];   // [bin][tid] : {count, p_sum}
    __shared__ bool   s_last;

    const int tid = threadIdx.x;
    #pragma unroll
    for (int b = 0; b < BINS; ++b)
        hist[b * NTHREADS + tid] = make_float2(0.0f, 0.0f);
    __syncthreads();

    float2* hist_tid = &hist[tid];
    const int stride = gridDim.x * NTHREADS;

    for (int i = blockIdx.x * NTHREADS + tid; i < nvec; i += stride) {
        float4 xv = xv4[i];
        float4 tv = tv4[i];
        ghm_elem(xv.x, tv.x, hist_tid);
        ghm_elem(xv.y, tv.y, hist_tid);
        ghm_elem(xv.z, tv.z, hist_tid);
        ghm_elem(xv.w, tv.w, hist_tid);
    }

    // scalar tail (n not multiple of 4) -- block 0 only
    if (blockIdx.x == 0) {
        int base = nvec * 4;
        if (base + tid < n) {
            const float* xf = (const float*)xv4;
            const float* tf = (const float*)tv4;
            ghm_elem(xf[base + tid], tf[base + tid], hist_tid);
        }
    }
    __syncthreads();

    // tree-reduce the 256 private histograms
    for (int s = NTHREADS / 2; s > 0; s >>= 1) {
        if (tid < s) {
            #pragma unroll
            for (int b = 0; b < BINS; ++b) {
                float2 a = hist[b * NTHREADS + tid];
                float2 c = hist[b * NTHREADS + tid + s];
                a.x += c.x;
                a.y += c.y;
                hist[b * NTHREADS + tid] = a;
            }
        }
        __syncthreads();
    }

    if (tid < BINS) {
        atomicAdd(&g_cnt[tid], (double)hist[tid * NTHREADS].x);
        atomicAdd(&g_sum[tid], (double)hist[tid * NTHREADS].y);
    }

    // last-block-done protocol
    __threadfence();
    if (tid == 0) {
        unsigned int prev = atomicAdd(&g_done, 1u);
        s_last = (prev == (unsigned int)(gridDim.x - 1));
    }
    __syncthreads();

    if (s_last && tid == 0) {
        __threadfence();   // acquire: make all blocks' atomics visible
        volatile double* vc = (volatile double*)g_cnt;
        volatile double* vs = (volatile double*)g_sum;
        double cnt[BINS], sum[BINS];
        double ne = 0.0;
        #pragma unroll
        for (int b = 0; b < BINS; ++b) {
            cnt[b] = vc[b];
            sum[b] = vs[b];
            if (cnt[b] > 0.0) ne += 1.0;
        }
        double res = 0.0;
        #pragma unroll
        for (int b = 0; b < BINS; ++b) {
            double gd = cnt[b] * ne;
            if (gd < 1e-4) gd = 1e-4;
            res += (sum[b] * LN2_D) / gd;
        }
        out[0] = (float)res;

        // reset for the next graph replay (deterministic re-execution)
        #pragma unroll
        for (int b = 0; b < BINS; ++b) { g_cnt[b] = 0.0; g_sum[b] = 0.0; }
        __threadfence();
        g_done = 0u;
    }
}

extern "C" void kernel_launch(void* const* d_in, const int* in_sizes, int n_in,
                              void* d_out, int out_size) {
    const float* x = (const float*)d_in[0];
    const float* t = (const float*)d_in[1];
    int n    = in_sizes[0];
    int nvec = n >> 2;

    ghm_fused_kernel<<<NBLOCKS, NTHREADS>>>((const float4*)x, (const float4*)t,
                                            nvec, n, (float*)d_out);
}

// round 7
// speedup vs baseline: 1.0653x; 1.0562x over previous
#include <cuda_runtime.h>
#include <cuda_bf16.h>

// GHM-C loss, fused single kernel (R7: slim math, no predicates, no F2I, 2x unroll).
//   t in {0,1} exact. nz2 = -z*log2e = x * (2t-1)*log2e
//   u = 2^{nz2}; w = 1+u; g = sigmoid(z) = 1/w; softplus(z)/ln2 = log2(w) - nz2
//   result = sum_b (ln2 * P_b) / max(cnt_b * nonempty, 1e-4)

#define BINS      10
#define NTHREADS  256
#define NBLOCKS   1036         // 148 SMs * 7 resident blocks -> 1 wave
#define LOG2E_F   1.4426950408889634f
#define LN2_D     0.6931471805599453
#define MAGIC_F   12582912.0f  // 1.5 * 2^23

__device__ double        g_cnt[BINS];   // zero-initialized at module load
__device__ double        g_sum[BINS];
__device__ unsigned int  g_done;

__device__ __forceinline__ void ghm_elem(float xk, float tk, char* hist_base)
{
    // nz2 = -z*log2e  (t exactly 0/1):  s = 2*L*t - L
    float s   = fmaf(tk, 2.0f * LOG2E_F, -LOG2E_F);
    float nz2 = xk * s;
    float u   = exp2f(nz2);                       // MUFU.EX2
    float w   = 1.0f + u;
    float r   = __frcp_rn(u + 1.0f) * 0.0f + __fdividef(1.0f, w); // placeholder removed below
    (void)r;
    float rr  = __fdividef(1.0f, w);              // MUFU.RCP (+FMUL folded: 1.0*rcp)
    // bin = floor(9.9999 * g) via magic-number round-to-nearest of (q - 0.5)
    float m   = fmaf(rr, 9.9999f, -0.5f) + MAGIC_F;
    int bits  = __float_as_int(m) & 0xF;          // 0..9
    float p   = __log2f(w) - nz2;                 // softplus(z)/ln2  (MUFU.LG2)

    float2* slot = (float2*)(hist_base + bits * (NTHREADS * 8));
    float2 h = *slot;
    h.x += 1.0f;
    h.y += p;
    *slot = h;
}

__global__ __launch_bounds__(NTHREADS, 7)
void ghm_fused_kernel(const float4* __restrict__ xv4,
                      const float4* __restrict__ tv4,
                      int nvec, int n,
                      float* __restrict__ out)
{
    __shared__ float2 hist[BINS * NTHREADS];   // [bin][tid] : {count, p_sum}
    __shared__ bool   s_last;

    const int tid = threadIdx.x;
    #pragma unroll
    for (int b = 0; b < BINS; ++b)
        hist[b * NTHREADS + tid] = make_float2(0.0f, 0.0f);
    __syncthreads();

    char* hist_base = (char*)&hist[tid];
    const int stride  = gridDim.x * NTHREADS;
    const int stride2 = stride * 2;

    int i = blockIdx.x * NTHREADS + tid;
    for (; i + stride < nvec; i += stride2) {
        // two independent load pairs in flight (4x LDG.128)
        float4 xa = __ldcs(&xv4[i]);
        float4 ta = __ldcs(&tv4[i]);
        float4 xb = __ldcs(&xv4[i + stride]);
        float4 tb = __ldcs(&tv4[i + stride]);
        ghm_elem(xa.x, ta.x, hist_base);
        ghm_elem(xa.y, ta.y, hist_base);
        ghm_elem(xa.z, ta.z, hist_base);
        ghm_elem(xa.w, ta.w, hist_base);
        ghm_elem(xb.x, tb.x, hist_base);
        ghm_elem(xb.y, tb.y, hist_base);
        ghm_elem(xb.z, tb.z, hist_base);
        ghm_elem(xb.w, tb.w, hist_base);
    }
    if (i < nvec) {
        float4 xa = __ldcs(&xv4[i]);
        float4 ta = __ldcs(&tv4[i]);
        ghm_elem(xa.x, ta.x, hist_base);
        ghm_elem(xa.y, ta.y, hist_base);
        ghm_elem(xa.z, ta.z, hist_base);
        ghm_elem(xa.w, ta.w, hist_base);
    }

    // scalar tail (n not multiple of 4) -- block 0 only
    if (blockIdx.x == 0) {
        int base = nvec * 4;
        if (base + tid < n) {
            const float* xf = (const float*)xv4;
            const float* tf = (const float*)tv4;
            ghm_elem(xf[base + tid], tf[base + tid], hist_base);
        }
    }
    __syncthreads();

    // tree-reduce the 256 private histograms
    for (int sred = NTHREADS / 2; sred > 0; sred >>= 1) {
        if (tid < sred) {
            #pragma unroll
            for (int b = 0; b < BINS; ++b) {
                float2 a = hist[b * NTHREADS + tid];
                float2 c = hist[b * NTHREADS + tid + sred];
                a.x += c.x;
                a.y += c.y;
                hist[b * NTHREADS + tid] = a;
            }
        }
        __syncthreads();
    }

    if (tid < BINS) {
        atomicAdd(&g_cnt[tid], (double)hist[tid * NTHREADS].x);
        atomicAdd(&g_sum[tid], (double)hist[tid * NTHREADS].y);
    }

    // last-block-done protocol
    __threadfence();
    if (tid == 0) {
        unsigned int prev = atomicAdd(&g_done, 1u);
        s_last = (prev == (unsigned int)(gridDim.x - 1));
    }
    __syncthreads();

    if (s_last && tid == 0) {
        __threadfence();   // acquire: make all blocks' atomics visible
        volatile double* vc = (volatile double*)g_cnt;
        volatile double* vs = (volatile double*)g_sum;
        double cnt[BINS], sum[BINS];
        double ne = 0.0;
        #pragma unroll
        for (int b = 0; b < BINS; ++b) {
            cnt[b] = vc[b];
            sum[b] = vs[b];
            if (cnt[b] > 0.0) ne += 1.0;
        }
        double res = 0.0;
        #pragma unroll
        for (int b = 0; b < BINS; ++b) {
            double gd = cnt[b] * ne;
            if (gd < 1e-4) gd = 1e-4;
            res += (sum[b] * LN2_D) / gd;
        }
        out[0] = (float)res;

        // reset for the next graph replay (deterministic re-execution)
        #pragma unroll
        for (int b = 0; b < BINS; ++b) { g_cnt[b] = 0.0; g_sum[b] = 0.0; }
        __threadfence();
        g_done = 0u;
    }
}

extern "C" void kernel_launch(void* const* d_in, const int* in_sizes, int n_in,
                              void* d_out, int out_size) {
    const float* x = (const float*)d_in[0];
    const float* t = (const float*)d_in[1];
    int n    = in_sizes[0];
    int nvec = n >> 2;

    ghm_fused_kernel<<<NBLOCKS, NTHREADS>>>((const float4*)x, (const float4*)t,
                                            nvec, n, (float*)d_out);
}